// round 2
// baseline (speedup 1.0000x reference)
#include <cuda_runtime.h>
#include <math.h>

#define BB 4
#define TT 32
#define NN 20000
#define NE 320000
#define DG 64
#define DW 300
#define DH 256
#define HD 128
#define H3 384
#define DESC 16
#define NC 2000

// ---------------- scratch (static device memory; no allocations) ----------------
__device__ float g_gx[2][BB][TT][H3];        // precomputed input gates (scan-step indexed)
__device__ float g_qemb[BB][DH];             // BiGRU output
__device__ float g_qg[BB][DG];               // q_emb @ W_hg + b_hg
__device__ float g_hb[NN][BB][DG];           // attn node feat projected through basis W0
__device__ float g_agg[NN][BB][DG];          // RGCN aggregation / post-relu node feats
__device__ float g_s[BB][NN];                // attn2 logits
__device__ float g_stats[BB][2];             // softmax max, 1/sum
__device__ float g_nodeagg[BB][DG];
__device__ float g_hidden[BB][1024];

// ---------------- kernel 0: zero accumulators ----------------
__global__ void k_zero() {
    int i = blockIdx.x * blockDim.x + threadIdx.x;
    const int total4 = NN * BB * DG / 4;  // 1,280,000
    float4* p = (float4*)&g_agg[0][0][0];
    if (i < total4) p[i] = make_float4(0.f, 0.f, 0.f, 0.f);
    if (i < BB * DG) ((float*)g_nodeagg)[i] = 0.f;
}

// ---------------- kernel 1a: gx_all = x @ Wx + bx (both directions) ----------------
// 16 blocks x 256 threads; each block handles 8 (b,t) pairs.
__global__ __launch_bounds__(256) void k_gx(
    const int* __restrict__ questions, const float* __restrict__ emb_word,
    const float* __restrict__ Wxf, const float* __restrict__ bxf,
    const float* __restrict__ Wxb, const float* __restrict__ bxb)
{
    __shared__ float xs[8][DW];
    __shared__ int toks[8];
    int tid = threadIdx.x;
    int p0 = blockIdx.x * 8;
    if (tid < 8) toks[tid] = questions[p0 + tid];
    __syncthreads();
    for (int i = tid; i < 8 * DW; i += 256) {
        int pp = i / DW, k = i % DW;
        xs[pp][k] = emb_word[(size_t)toks[pp] * DW + k];
    }
    __syncthreads();
    for (int o = tid; o < 8 * 2 * H3; o += 256) {
        int pp = o / (2 * H3);
        int g  = o % (2 * H3);
        int dir = g / H3, gg = g % H3;
        const float* Wx = dir ? Wxb : Wxf;
        float acc = (dir ? bxb : bxf)[gg];
        const float* x = xs[pp];
#pragma unroll 4
        for (int i = 0; i < DW; i++) acc += x[i] * Wx[i * H3 + gg];
        int bt = p0 + pp;
        int b = bt / TT, t = bt % TT;
        int ts = dir ? (TT - 1 - t) : t;   // scan-step index
        g_gx[dir][b][ts][gg] = acc;
    }
}

// ---------------- kernel 1b: GRU scan (8 blocks: dir x batch), 384 threads ----------------
__global__ __launch_bounds__(384) void k_gru(
    const int* __restrict__ questions,
    const float* __restrict__ Whf, const float* __restrict__ bhf,
    const float* __restrict__ Whb, const float* __restrict__ bhb)
{
    int blk = blockIdx.x;
    int dir = blk >> 2, b = blk & 3;
    const float* Wh = dir ? Whb : Whf;
    const float* bh = dir ? bhb : bhf;
    int tid = threadIdx.x;  // 0..383: (gate, unit)
    __shared__ float hs[HD];
    __shared__ float gsh[H3];
    if (tid < HD) hs[tid] = 0.f;
    float bias = bh[tid];
    __syncthreads();
    for (int t = 0; t < TT; t++) {
        float acc = bias;
#pragma unroll 8
        for (int k = 0; k < HD; k++) acc += hs[k] * Wh[k * H3 + tid];
        gsh[tid] = acc;
        __syncthreads();
        if (tid < HD) {
            const float* gx = &g_gx[dir][b][t][0];
            float r = 1.f / (1.f + expf(-(gx[tid] + gsh[tid])));
            float z = 1.f / (1.f + expf(-(gx[HD + tid] + gsh[HD + tid])));
            float n = tanhf(gx[2 * HD + tid] + r * gsh[2 * HD + tid]);
            float h = hs[tid];
            float hnew = (1.f - z) * n + z * h;
            int torig = dir ? (TT - 1 - t) : t;
            hs[tid] = (questions[b * TT + torig] != 0) ? hnew : h;
        }
        __syncthreads();
    }
    if (tid < HD) g_qemb[b][dir * HD + tid] = hs[tid];
}

// ---------------- kernel 1c: q_g = q_emb @ W_hg + b_hg ----------------
__global__ void k_qg(const float* __restrict__ Whg, const float* __restrict__ bhg) {
    int tid = threadIdx.x;  // 256 threads, 1 block
    int b = tid / DG, o = tid % DG;
    float acc = bhg[o];
#pragma unroll 8
    for (int i = 0; i < DH; i++) acc += g_qemb[b][i] * Whg[i * DG + o];
    g_qg[b][o] = acc;
}

// ---------------- kernel 2: node attention + basis projection ----------------
// one warp per node; 5000 blocks x 128 threads
__global__ __launch_bounds__(128) void k_nodefeat(
    const int* __restrict__ node_descs, const float* __restrict__ emb_desc,
    const float* __restrict__ bases)
{
    __shared__ float sW0[DG][DG];              // 16KB
    __shared__ float sQg[BB][DG];              // 1KB
    __shared__ float sDesc[4][DESC][DG + 2];   // padded: ~16.9KB
    __shared__ float sLog[4][BB * DESC];       // 1KB
    __shared__ float sWt[4][BB][DESC];         // 1KB
    __shared__ float sF[4][BB][DG];            // 4KB
    int tid = threadIdx.x;
    for (int i = tid; i < DG * DG; i += 128) ((float*)sW0)[i] = bases[i];
    for (int i = tid; i < BB * DG; i += 128) ((float*)sQg)[i] = ((const float*)g_qg)[i];
    __syncthreads();

    int w = tid >> 5, lane = tid & 31;
    int n = blockIdx.x * 4 + w;
    if (n >= NN) return;

    int tok = 0;
    if (lane < DESC) tok = node_descs[n * DESC + lane];
#pragma unroll
    for (int i = 0; i < DESC; i++) {
        int ti = __shfl_sync(0xffffffffu, tok, i);
        float2 v = ((const float2*)(emb_desc + (size_t)ti * DG))[lane];
        *(float2*)&sDesc[w][i][2 * lane] = v;
    }
    __syncwarp();

    // logits: lane computes pairs p = 2*lane, 2*lane+1; p -> (b = p>>4, i = p&15)
#pragma unroll
    for (int p2 = 0; p2 < 2; p2++) {
        int p = 2 * lane + p2;
        int b = p >> 4, i = p & 15;
        float acc = 0.f;
#pragma unroll
        for (int d = 0; d < DG; d++) acc += sDesc[w][i][d] * sQg[b][d];
        sLog[w][p] = acc;
    }
    __syncwarp();

    if (lane < BB) {
        float m = -1e30f;
#pragma unroll
        for (int i = 0; i < DESC; i++) m = fmaxf(m, sLog[w][lane * 16 + i]);
        float e[DESC];
        float s = 0.f;
#pragma unroll
        for (int i = 0; i < DESC; i++) { e[i] = expf(sLog[w][lane * 16 + i] - m); s += e[i]; }
        float inv = 1.f / s;
#pragma unroll
        for (int i = 0; i < DESC; i++) sWt[w][lane][i] = e[i] * inv;
    }
    __syncwarp();

    // f[b][d] = sum_i wt[b][i]*desc[i][d]; lane owns dims 2*lane, 2*lane+1
#pragma unroll
    for (int b = 0; b < BB; b++) {
        float a0 = 0.f, a1 = 0.f;
#pragma unroll
        for (int i = 0; i < DESC; i++) {
            float wt = sWt[w][b][i];
            float2 dv = *(float2*)&sDesc[w][i][2 * lane];
            a0 += wt * dv.x;
            a1 += wt * dv.y;
        }
        *(float2*)&sF[w][b][2 * lane] = make_float2(a0, a1);
    }
    __syncwarp();

    // basis projection: out[b][d'] = sum_d f[b][d] * W0[d][d']; lane owns d' = 2*lane..+1
    float acc[BB][2] = {};
#pragma unroll
    for (int d = 0; d < DG; d++) {
        float2 wv = *(float2*)&sW0[d][2 * lane];
#pragma unroll
        for (int b = 0; b < BB; b++) {
            float fv = sF[w][b][d];
            acc[b][0] += fv * wv.x;
            acc[b][1] += fv * wv.y;
        }
    }
#pragma unroll
    for (int b = 0; b < BB; b++)
        *(float2*)&g_hb[n][b][2 * lane] = make_float2(acc[b][0], acc[b][1]);
}

// ---------------- kernel 3: edge scatter (RGCN message passing) ----------------
// 16 threads per edge (one float4 dim-quad each), loop over batches.
__global__ __launch_bounds__(256) void k_scatter(
    const int* __restrict__ esrc, const int* __restrict__ edst,
    const int* __restrict__ etype, const float* __restrict__ wcomp)
{
    int gid = blockIdx.x * blockDim.x + threadIdx.x;
    int e = gid >> 4, q = gid & 15;
    if (e >= NE) return;
    int src = esrc[e], dst = edst[e];
    float c = wcomp[etype[e]];
#pragma unroll
    for (int b = 0; b < BB; b++) {
        float4 v = ((const float4*)&g_hb[src][b][0])[q];
        float4 m = make_float4(c * v.x, c * v.y, c * v.z, c * v.w);
        atomicAdd(((float4*)&g_agg[dst][b][0]) + q, m);
    }
}

// ---------------- kernel 4: relu(agg+bias) in place + attn2 logits ----------------
__global__ __launch_bounds__(256) void k_relu_logit(const float* __restrict__ rbias) {
    int w = threadIdx.x >> 5, lane = threadIdx.x & 31;
    int n = blockIdx.x * 8 + w;
    if (n >= NN) return;
    int d0 = 2 * lane;
    float b0 = rbias[d0], b1 = rbias[d0 + 1];
    float dot[BB];
#pragma unroll
    for (int b = 0; b < BB; b++) {
        float2 v = *(float2*)&g_agg[n][b][d0];
        v.x = fmaxf(v.x + b0, 0.f);
        v.y = fmaxf(v.y + b1, 0.f);
        *(float2*)&g_agg[n][b][d0] = v;
        dot[b] = v.x * g_qg[b][d0] + v.y * g_qg[b][d0 + 1];
    }
#pragma unroll
    for (int off = 16; off; off >>= 1) {
#pragma unroll
        for (int b = 0; b < BB; b++)
            dot[b] += __shfl_down_sync(0xffffffffu, dot[b], off);
    }
    if (lane == 0) {
#pragma unroll
        for (int b = 0; b < BB; b++) g_s[b][n] = dot[b];
    }
}

// ---------------- kernel 5: softmax stats over nodes (4 blocks) ----------------
__global__ __launch_bounds__(512) void k_stats() {
    int b = blockIdx.x, tid = threadIdx.x;
    __shared__ float red[512];
    float m = -1e30f;
    for (int n = tid; n < NN; n += 512) m = fmaxf(m, g_s[b][n]);
    red[tid] = m;
    __syncthreads();
    for (int s = 256; s; s >>= 1) {
        if (tid < s) red[tid] = fmaxf(red[tid], red[tid + s]);
        __syncthreads();
    }
    m = red[0];
    __syncthreads();
    float sum = 0.f;
    for (int n = tid; n < NN; n += 512) sum += expf(g_s[b][n] - m);
    red[tid] = sum;
    __syncthreads();
    for (int s = 256; s; s >>= 1) {
        if (tid < s) red[tid] += red[tid + s];
        __syncthreads();
    }
    if (tid == 0) { g_stats[b][0] = m; g_stats[b][1] = 1.f / red[0]; }
}

// ---------------- kernel 6: attention pooling over nodes ----------------
#define CH 256
__global__ __launch_bounds__(256) void k_pool() {
    const int nch = (NN + CH - 1) / CH;  // 79
    int b = blockIdx.x / nch, c = blockIdx.x % nch;
    int n0 = c * CH;
    __shared__ float p[CH];
    __shared__ float part[4][DG];
    int tid = threadIdx.x;
    float m = g_stats[b][0], inv = g_stats[b][1];
    int n = n0 + tid;
    p[tid] = (n < NN) ? expf(g_s[b][n] - m) * inv : 0.f;
    __syncthreads();
    int d = tid & 63, g = tid >> 6;
    float acc = 0.f;
    for (int nl = g; nl < CH; nl += 4) {
        int nn2 = n0 + nl;
        if (nn2 < NN) acc += p[nl] * g_agg[nn2][b][d];
    }
    part[g][d] = acc;
    __syncthreads();
    if (tid < DG)
        atomicAdd(&g_nodeagg[b][tid], part[0][tid] + part[1][tid] + part[2][tid] + part[3][tid]);
}

// ---------------- kernel 7: classifier ----------------
__global__ __launch_bounds__(256) void k_fc1(const float* __restrict__ W1, const float* __restrict__ b1) {
    __shared__ float feat[BB][DG + DH];  // [4][320]
    int tid = threadIdx.x;
    for (int i = tid; i < BB * (DG + DH); i += 256) {
        int b = i / (DG + DH), k = i % (DG + DH);
        feat[b][k] = (k < DG) ? g_nodeagg[b][k] : g_qemb[b][k - DG];
    }
    __syncthreads();
    int j = blockIdx.x * 256 + tid;  // 4 blocks -> 1024
    float acc[BB] = {};
    for (int i = 0; i < DG + DH; i++) {
        float w = W1[i * 1024 + j];
#pragma unroll
        for (int b = 0; b < BB; b++) acc[b] += feat[b][i] * w;
    }
    float bj = b1[j];
#pragma unroll
    for (int b = 0; b < BB; b++) g_hidden[b][j] = fmaxf(acc[b] + bj, 0.f);
}

__global__ __launch_bounds__(256) void k_fc2(const float* __restrict__ W2, const float* __restrict__ b2,
                                             float* __restrict__ out) {
    __shared__ float h[BB][1024];  // 16KB
    int tid = threadIdx.x;
    for (int i = tid; i < BB * 1024; i += 256) ((float*)h)[i] = ((const float*)g_hidden)[i];
    __syncthreads();
    int j = blockIdx.x * 256 + tid;  // 8 blocks -> 2048
    if (j >= NC) return;
    float acc[BB] = {};
    for (int i = 0; i < 1024; i++) {
        float w = W2[i * NC + j];
#pragma unroll
        for (int b = 0; b < BB; b++) acc[b] += h[b][i] * w;
    }
    float bj = b2[j];
#pragma unroll
    for (int b = 0; b < BB; b++) out[b * NC + j] = acc[b] + bj;
}

// ---------------- launch ----------------
extern "C" void kernel_launch(void* const* d_in, const int* in_sizes, int n_in,
                              void* d_out, int out_size) {
    const int*   questions  = (const int*)d_in[0];
    const int*   node_descs = (const int*)d_in[1];
    const int*   edge_src   = (const int*)d_in[2];
    const int*   edge_dst   = (const int*)d_in[3];
    const int*   edge_type  = (const int*)d_in[4];
    const float* emb_word   = (const float*)d_in[5];
    const float* emb_desc   = (const float*)d_in[6];
    const float* Wx_f       = (const float*)d_in[7];
    const float* Wh_f       = (const float*)d_in[8];
    const float* bx_f       = (const float*)d_in[9];
    const float* bh_f       = (const float*)d_in[10];
    const float* Wx_b       = (const float*)d_in[11];
    const float* Wh_b       = (const float*)d_in[12];
    const float* bx_b       = (const float*)d_in[13];
    const float* bh_b       = (const float*)d_in[14];
    const float* W_hg       = (const float*)d_in[15];
    const float* b_hg       = (const float*)d_in[16];
    const float* bases      = (const float*)d_in[17];
    const float* w_comp     = (const float*)d_in[18];
    const float* rgcn_bias  = (const float*)d_in[19];
    const float* W1         = (const float*)d_in[20];
    const float* b1         = (const float*)d_in[21];
    const float* W2         = (const float*)d_in[22];
    const float* b2         = (const float*)d_in[23];
    float* out = (float*)d_out;

    k_zero<<<(NN * BB * DG / 4 + 255) / 256, 256>>>();
    k_gx<<<16, 256>>>(questions, emb_word, Wx_f, bx_f, Wx_b, bx_b);
    k_gru<<<8, 384>>>(questions, Wh_f, bh_f, Wh_b, bh_b);
    k_qg<<<1, 256>>>(W_hg, b_hg);
    k_nodefeat<<<(NN + 3) / 4, 128>>>(node_descs, emb_desc, bases);
    k_scatter<<<(NE * 16 + 255) / 256, 256>>>(edge_src, edge_dst, edge_type, w_comp);
    k_relu_logit<<<(NN + 7) / 8, 256>>>(rgcn_bias);
    k_stats<<<4, 512>>>();
    k_pool<<<4 * ((NN + CH - 1) / CH), 256>>>();
    k_fc1<<<4, 256>>>(W1, b1);
    k_fc2<<<8, 256>>>(W2, b2, out);
}

// round 3
// speedup vs baseline: 1.1436x; 1.1436x over previous
#include <cuda_runtime.h>
#include <math.h>

#define BB 4
#define TT 32
#define NN 20000
#define NE 320000
#define DG 64
#define DW 300
#define DH 256
#define HD 128
#define H3 384
#define DESC 16
#define NC 2000

// ---------------- scratch (static device memory; no allocations) ----------------
__device__ float g_gx[2][BB][TT][H3];        // precomputed input gates (scan-step indexed)
__device__ float g_qemb[BB][DH];             // BiGRU output
__device__ float g_qg[BB][DG];               // q_emb @ W_hg + b_hg
__device__ float g_hb[NN][BB][DG];           // attn node feat projected through basis W0
__device__ float g_agg[NN][BB][DG];          // RGCN post-relu node feats
__device__ float g_s[BB][NN];                // attn2 logits
__device__ float g_stats[BB][2];             // softmax max, 1/sum
__device__ float g_nodeagg[BB][DG];
__device__ float g_hidden[BB][1024];
// CSR-by-destination
__device__ int   g_deg[NN];
__device__ int   g_off[NN + 1];
__device__ int   g_cur[NN];
__device__ int   g_csrc[NE];
__device__ float g_cc[NE];

// ---------------- kernel 0: zero deg / nodeagg / out ----------------
__global__ void k_zero(float* __restrict__ out) {
    int i = blockIdx.x * blockDim.x + threadIdx.x;
    if (i < NN) g_deg[i] = 0;
    if (i < BB * NC) out[i] = 0.f;
    if (i < BB * DG) ((float*)g_nodeagg)[i] = 0.f;
}

// ---------------- CSR build ----------------
__global__ __launch_bounds__(256) void k_hist(const int* __restrict__ edst) {
    int e = blockIdx.x * 256 + threadIdx.x;
    if (e < NE) atomicAdd(&g_deg[edst[e]], 1);
}

__global__ __launch_bounds__(1024) void k_scan() {
    __shared__ int part[1024];
    int t = threadIdx.x;
    const int CHK = 20;  // 1024*20 >= 20000
    int base = t * CHK;
    int s = 0;
#pragma unroll
    for (int k = 0; k < CHK; k++) { int idx = base + k; if (idx < NN) s += g_deg[idx]; }
    part[t] = s;
    __syncthreads();
    for (int off = 1; off < 1024; off <<= 1) {
        int v = (t >= off) ? part[t - off] : 0;
        __syncthreads();
        part[t] += v;
        __syncthreads();
    }
    int run = part[t] - s;  // exclusive prefix
#pragma unroll
    for (int k = 0; k < CHK; k++) {
        int idx = base + k;
        if (idx < NN) { g_off[idx] = run; g_cur[idx] = run; run += g_deg[idx]; }
    }
    if (t == 1023) g_off[NN] = part[1023];
}

__global__ __launch_bounds__(256) void k_fill(
    const int* __restrict__ esrc, const int* __restrict__ edst,
    const int* __restrict__ etype, const float* __restrict__ wcomp) {
    int e = blockIdx.x * 256 + threadIdx.x;
    if (e >= NE) return;
    int d = edst[e];
    int pos = atomicAdd(&g_cur[d], 1);
    g_csrc[pos] = esrc[e];
    g_cc[pos] = wcomp[etype[e]];
}

// ---------------- kernel 1a: gx_all = x @ Wx + bx (both directions) ----------------
__global__ __launch_bounds__(256) void k_gx(
    const int* __restrict__ questions, const float* __restrict__ emb_word,
    const float* __restrict__ Wxf, const float* __restrict__ bxf,
    const float* __restrict__ Wxb, const float* __restrict__ bxb)
{
    __shared__ float xs[8][DW];
    __shared__ int toks[8];
    int tid = threadIdx.x;
    int p0 = blockIdx.x * 8;
    if (tid < 8) toks[tid] = questions[p0 + tid];
    __syncthreads();
    for (int i = tid; i < 8 * DW; i += 256) {
        int pp = i / DW, k = i % DW;
        xs[pp][k] = emb_word[(size_t)toks[pp] * DW + k];
    }
    __syncthreads();
    for (int o = tid; o < 8 * 2 * H3; o += 256) {
        int pp = o / (2 * H3);
        int g  = o % (2 * H3);
        int dir = g / H3, gg = g % H3;
        const float* Wx = dir ? Wxb : Wxf;
        float acc = (dir ? bxb : bxf)[gg];
        const float* x = xs[pp];
#pragma unroll 4
        for (int i = 0; i < DW; i++) acc += x[i] * Wx[i * H3 + gg];
        int bt = p0 + pp;
        int b = bt / TT, t = bt % TT;
        int ts = dir ? (TT - 1 - t) : t;
        g_gx[dir][b][ts][gg] = acc;
    }
}

// ---------------- kernel 1b: GRU scan, Wh register-resident ----------------
// 8 blocks (dir x batch) x 768 threads; 2 threads per output column, 64 weights each.
__global__ __launch_bounds__(768, 1) void k_gru(
    const int* __restrict__ questions,
    const float* __restrict__ Whf, const float* __restrict__ bhf,
    const float* __restrict__ Whb, const float* __restrict__ bhb)
{
    int blk = blockIdx.x;
    int dir = blk >> 2, b = blk & 3;
    const float* Wh = dir ? Whb : Whf;
    const float* bh = dir ? bhb : bhf;
    int tid = threadIdx.x;
    int col = tid >> 1, half = tid & 1;
    float w[64];
#pragma unroll
    for (int k = 0; k < 64; k++) w[k] = Wh[(half * 64 + k) * H3 + col];
    float bias = bh[col];
    __shared__ float hs[HD];
    __shared__ float gsh[H3];
    __shared__ int msk[TT];
    if (tid < HD) hs[tid] = 0.f;
    if (tid < TT) msk[tid] = questions[b * TT + tid];
    __syncthreads();
    for (int t = 0; t < TT; t++) {
        float acc = 0.f;
#pragma unroll
        for (int k = 0; k < 64; k++) acc += hs[half * 64 + k] * w[k];
        acc += __shfl_xor_sync(0xffffffffu, acc, 1);
        if (half == 0) gsh[col] = acc + bias;
        __syncthreads();
        if (tid < HD) {
            const float* gx = &g_gx[dir][b][t][0];
            float r = 1.f / (1.f + expf(-(gx[tid] + gsh[tid])));
            float z = 1.f / (1.f + expf(-(gx[HD + tid] + gsh[HD + tid])));
            float n = tanhf(gx[2 * HD + tid] + r * gsh[2 * HD + tid]);
            float h = hs[tid];
            float hnew = (1.f - z) * n + z * h;
            int torig = dir ? (TT - 1 - t) : t;
            hs[tid] = (msk[torig] != 0) ? hnew : h;
        }
        __syncthreads();
    }
    if (tid < HD) g_qemb[b][dir * HD + tid] = hs[tid];
}

// ---------------- kernel 1c: q_g = q_emb @ W_hg + b_hg (32 blocks) ----------------
__global__ __launch_bounds__(256) void k_qg(const float* __restrict__ Whg, const float* __restrict__ bhg) {
    int blk = blockIdx.x;
    int b = blk >> 3, og = blk & 7;     // 8 outputs per block
    int i = threadIdx.x;                // reduction dim 0..255
    float x = g_qemb[b][i];
    const float4* W4 = (const float4*)Whg;  // [256][16]
    float4 wA = W4[i * 16 + og * 2];
    float4 wB = W4[i * 16 + og * 2 + 1];
    float p[8] = { x * wA.x, x * wA.y, x * wA.z, x * wA.w,
                   x * wB.x, x * wB.y, x * wB.z, x * wB.w };
#pragma unroll
    for (int o = 0; o < 8; o++)
#pragma unroll
        for (int off = 16; off; off >>= 1)
            p[o] += __shfl_down_sync(0xffffffffu, p[o], off);
    __shared__ float red[8][8];
    int wid = i >> 5, lane = i & 31;
    if (lane == 0)
#pragma unroll
        for (int o = 0; o < 8; o++) red[o][wid] = p[o];
    __syncthreads();
    if (i < 8) {
        float s = bhg[og * 8 + i];
#pragma unroll
        for (int k = 0; k < 8; k++) s += red[i][k];
        g_qg[b][og * 8 + i] = s;
    }
}

// ---------------- kernel 2: node attention + basis projection ----------------
__global__ __launch_bounds__(128) void k_nodefeat(
    const int* __restrict__ node_descs, const float* __restrict__ emb_desc,
    const float* __restrict__ bases)
{
    __shared__ float sW0[DG][DG];
    __shared__ float sQg[BB][DG];
    __shared__ float sDesc[4][DESC][DG + 2];
    __shared__ float sLog[4][BB * DESC];
    __shared__ float sWt[4][BB][DESC];
    __shared__ float sF[4][BB][DG];
    int tid = threadIdx.x;
    for (int i = tid; i < DG * DG; i += 128) ((float*)sW0)[i] = bases[i];
    for (int i = tid; i < BB * DG; i += 128) ((float*)sQg)[i] = ((const float*)g_qg)[i];
    __syncthreads();

    int w = tid >> 5, lane = tid & 31;
    int n = blockIdx.x * 4 + w;
    if (n >= NN) return;

    int tok = 0;
    if (lane < DESC) tok = node_descs[n * DESC + lane];
#pragma unroll
    for (int i = 0; i < DESC; i++) {
        int ti = __shfl_sync(0xffffffffu, tok, i);
        float2 v = ((const float2*)(emb_desc + (size_t)ti * DG))[lane];
        *(float2*)&sDesc[w][i][2 * lane] = v;
    }
    __syncwarp();

#pragma unroll
    for (int p2 = 0; p2 < 2; p2++) {
        int p = 2 * lane + p2;
        int b = p >> 4, i = p & 15;
        float acc = 0.f;
#pragma unroll
        for (int d = 0; d < DG; d++) acc += sDesc[w][i][d] * sQg[b][d];
        sLog[w][p] = acc;
    }
    __syncwarp();

    if (lane < BB) {
        float m = -1e30f;
#pragma unroll
        for (int i = 0; i < DESC; i++) m = fmaxf(m, sLog[w][lane * 16 + i]);
        float e[DESC];
        float s = 0.f;
#pragma unroll
        for (int i = 0; i < DESC; i++) { e[i] = expf(sLog[w][lane * 16 + i] - m); s += e[i]; }
        float inv = 1.f / s;
#pragma unroll
        for (int i = 0; i < DESC; i++) sWt[w][lane][i] = e[i] * inv;
    }
    __syncwarp();

#pragma unroll
    for (int b = 0; b < BB; b++) {
        float a0 = 0.f, a1 = 0.f;
#pragma unroll
        for (int i = 0; i < DESC; i++) {
            float wt = sWt[w][b][i];
            float2 dv = *(float2*)&sDesc[w][i][2 * lane];
            a0 += wt * dv.x;
            a1 += wt * dv.y;
        }
        *(float2*)&sF[w][b][2 * lane] = make_float2(a0, a1);
    }
    __syncwarp();

    float acc[BB][2] = {};
#pragma unroll
    for (int d = 0; d < DG; d++) {
        float2 wv = *(float2*)&sW0[d][2 * lane];
#pragma unroll
        for (int b = 0; b < BB; b++) {
            float fv = sF[w][b][d];
            acc[b][0] += fv * wv.x;
            acc[b][1] += fv * wv.y;
        }
    }
#pragma unroll
    for (int b = 0; b < BB; b++)
        *(float2*)&g_hb[n][b][2 * lane] = make_float2(acc[b][0], acc[b][1]);
}

// ---------------- kernel 3: CSR gather (RGCN aggregation) + bias/relu + attn2 logits ----------------
// one warp per destination node
__global__ __launch_bounds__(256) void k_gather(const float* __restrict__ rbias) {
    int w = threadIdx.x >> 5, lane = threadIdx.x & 31;
    int n = blockIdx.x * 8 + w;
    if (n >= NN) return;
    int off = g_off[n], end = g_off[n + 1];
    float4 a0 = make_float4(0.f, 0.f, 0.f, 0.f);
    float4 a1 = make_float4(0.f, 0.f, 0.f, 0.f);
    const float4* hb4 = (const float4*)g_hb;
    for (int base = off; base < end; base += 32) {
        int ii = base + lane;
        int src = (ii < end) ? g_csrc[ii] : 0;
        float cc = (ii < end) ? g_cc[ii] : 0.f;
        int m = min(32, end - base);
        for (int j = 0; j < m; j++) {
            int s = __shfl_sync(0xffffffffu, src, j);
            float c = __shfl_sync(0xffffffffu, cc, j);
            float4 v0 = hb4[s * 64 + lane];
            float4 v1 = hb4[s * 64 + 32 + lane];
            a0.x += c * v0.x; a0.y += c * v0.y; a0.z += c * v0.z; a0.w += c * v0.w;
            a1.x += c * v1.x; a1.y += c * v1.y; a1.z += c * v1.z; a1.w += c * v1.w;
        }
    }
    // bias + relu (dim pattern repeats every 64 floats => same bias quad for both halves)
    const float4* rb4 = (const float4*)rbias;
    float4 rb = rb4[lane & 15];
    a0.x = fmaxf(a0.x + rb.x, 0.f); a0.y = fmaxf(a0.y + rb.y, 0.f);
    a0.z = fmaxf(a0.z + rb.z, 0.f); a0.w = fmaxf(a0.w + rb.w, 0.f);
    a1.x = fmaxf(a1.x + rb.x, 0.f); a1.y = fmaxf(a1.y + rb.y, 0.f);
    a1.z = fmaxf(a1.z + rb.z, 0.f); a1.w = fmaxf(a1.w + rb.w, 0.f);
    float4* agg4 = (float4*)g_agg;
    agg4[n * 64 + lane] = a0;
    agg4[n * 64 + 32 + lane] = a1;
    // attn2 logits: a0 covers batches 0/1 (lanes 0-15 / 16-31), a1 covers 2/3
    const float4* qg4 = (const float4*)g_qg;
    float4 q0 = qg4[lane];
    float4 q1 = qg4[lane + 32];
    float p0 = a0.x * q0.x + a0.y * q0.y + a0.z * q0.z + a0.w * q0.w;
    float p1 = a1.x * q1.x + a1.y * q1.y + a1.z * q1.z + a1.w * q1.w;
#pragma unroll
    for (int o = 8; o; o >>= 1) {
        p0 += __shfl_down_sync(0xffffffffu, p0, o, 16);
        p1 += __shfl_down_sync(0xffffffffu, p1, o, 16);
    }
    if (lane == 0)  { g_s[0][n] = p0; g_s[2][n] = p1; }
    if (lane == 16) { g_s[1][n] = p0; g_s[3][n] = p1; }
}

// ---------------- kernel 5: softmax stats over nodes (4 blocks) ----------------
__global__ __launch_bounds__(512) void k_stats() {
    int b = blockIdx.x, tid = threadIdx.x;
    __shared__ float red[512];
    float m = -1e30f;
    for (int n = tid; n < NN; n += 512) m = fmaxf(m, g_s[b][n]);
    red[tid] = m;
    __syncthreads();
    for (int s = 256; s; s >>= 1) {
        if (tid < s) red[tid] = fmaxf(red[tid], red[tid + s]);
        __syncthreads();
    }
    m = red[0];
    __syncthreads();
    float sum = 0.f;
    for (int n = tid; n < NN; n += 512) sum += expf(g_s[b][n] - m);
    red[tid] = sum;
    __syncthreads();
    for (int s = 256; s; s >>= 1) {
        if (tid < s) red[tid] += red[tid + s];
        __syncthreads();
    }
    if (tid == 0) { g_stats[b][0] = m; g_stats[b][1] = 1.f / red[0]; }
}

// ---------------- kernel 6: attention pooling over nodes ----------------
#define CH 256
__global__ __launch_bounds__(256) void k_pool() {
    const int nch = (NN + CH - 1) / CH;
    int b = blockIdx.x / nch, c = blockIdx.x % nch;
    int n0 = c * CH;
    __shared__ float p[CH];
    __shared__ float part[4][DG];
    int tid = threadIdx.x;
    float m = g_stats[b][0], inv = g_stats[b][1];
    int n = n0 + tid;
    p[tid] = (n < NN) ? expf(g_s[b][n] - m) * inv : 0.f;
    __syncthreads();
    int d = tid & 63, g = tid >> 6;
    float acc = 0.f;
    for (int nl = g; nl < CH; nl += 4) {
        int nn2 = n0 + nl;
        if (nn2 < NN) acc += p[nl] * g_agg[nn2][b][d];
    }
    part[g][d] = acc;
    __syncthreads();
    if (tid < DG)
        atomicAdd(&g_nodeagg[b][tid], part[0][tid] + part[1][tid] + part[2][tid] + part[3][tid]);
}

// ---------------- kernel 7: classifier ----------------
__global__ __launch_bounds__(256) void k_fc1(const float* __restrict__ W1, const float* __restrict__ b1) {
    __shared__ float feat[BB][DG + DH];
    int tid = threadIdx.x;
    for (int i = tid; i < BB * (DG + DH); i += 256) {
        int b = i / (DG + DH), k = i % (DG + DH);
        feat[b][k] = (k < DG) ? g_nodeagg[b][k] : g_qemb[b][k - DG];
    }
    __syncthreads();
    int j = blockIdx.x * 256 + tid;
    float acc[BB] = {};
    for (int i = 0; i < DG + DH; i++) {
        float w = W1[i * 1024 + j];
#pragma unroll
        for (int b = 0; b < BB; b++) acc[b] += feat[b][i] * w;
    }
    float bj = b1[j];
#pragma unroll
    for (int b = 0; b < BB; b++) g_hidden[b][j] = fmaxf(acc[b] + bj, 0.f);
}

// split-K fc2: 8 j-blocks x 4 i-chunks, atomic combine into pre-zeroed out
__global__ __launch_bounds__(256) void k_fc2(const float* __restrict__ W2, const float* __restrict__ b2,
                                             float* __restrict__ out) {
    int jb = blockIdx.x & 7, chunk = blockIdx.x >> 3;
    __shared__ float h[BB][256];
    int tid = threadIdx.x;
    for (int idx = tid; idx < BB * 256; idx += 256) {
        int b = idx >> 8, ii = idx & 255;
        h[b][ii] = g_hidden[b][chunk * 256 + ii];
    }
    __syncthreads();
    int j = jb * 256 + tid;
    if (j >= NC) return;
    float acc[BB] = {};
    for (int i = 0; i < 256; i++) {
        float w = W2[(size_t)(chunk * 256 + i) * NC + j];
#pragma unroll
        for (int b = 0; b < BB; b++) acc[b] += h[b][i] * w;
    }
    float bj = (chunk == 0) ? b2[j] : 0.f;
#pragma unroll
    for (int b = 0; b < BB; b++) atomicAdd(&out[b * NC + j], acc[b] + bj);
}

// ---------------- launch ----------------
extern "C" void kernel_launch(void* const* d_in, const int* in_sizes, int n_in,
                              void* d_out, int out_size) {
    const int*   questions  = (const int*)d_in[0];
    const int*   node_descs = (const int*)d_in[1];
    const int*   edge_src   = (const int*)d_in[2];
    const int*   edge_dst   = (const int*)d_in[3];
    const int*   edge_type  = (const int*)d_in[4];
    const float* emb_word   = (const float*)d_in[5];
    const float* emb_desc   = (const float*)d_in[6];
    const float* Wx_f       = (const float*)d_in[7];
    const float* Wh_f       = (const float*)d_in[8];
    const float* Wh_b       = (const float*)d_in[12];
    const float* Wx_b       = (const float*)d_in[11];
    const float* bx_f       = (const float*)d_in[9];
    const float* bh_f       = (const float*)d_in[10];
    const float* bx_b       = (const float*)d_in[13];
    const float* bh_b       = (const float*)d_in[14];
    const float* W_hg       = (const float*)d_in[15];
    const float* b_hg       = (const float*)d_in[16];
    const float* bases      = (const float*)d_in[17];
    const float* w_comp     = (const float*)d_in[18];
    const float* rgcn_bias  = (const float*)d_in[19];
    const float* W1         = (const float*)d_in[20];
    const float* b1         = (const float*)d_in[21];
    const float* W2         = (const float*)d_in[22];
    const float* b2         = (const float*)d_in[23];
    float* out = (float*)d_out;

    k_zero<<<(NN + 255) / 256, 256>>>(out);
    k_hist<<<(NE + 255) / 256, 256>>>(edge_dst);
    k_scan<<<1, 1024>>>();
    k_fill<<<(NE + 255) / 256, 256>>>(edge_src, edge_dst, edge_type, w_comp);
    k_gx<<<16, 256>>>(questions, emb_word, Wx_f, bx_f, Wx_b, bx_b);
    k_gru<<<8, 768>>>(questions, Wh_f, bh_f, Wh_b, bh_b);
    k_qg<<<32, 256>>>(W_hg, b_hg);
    k_nodefeat<<<(NN + 3) / 4, 128>>>(node_descs, emb_desc, bases);
    k_gather<<<(NN + 7) / 8, 256>>>(rgcn_bias);
    k_stats<<<4, 512>>>();
    k_pool<<<4 * ((NN + CH - 1) / CH), 256>>>();
    k_fc1<<<4, 256>>>(W1, b1);
    k_fc2<<<32, 256>>>(W2, b2, out);
}

// round 4
// speedup vs baseline: 2.0825x; 1.8210x over previous
#include <cuda_runtime.h>
#include <math.h>

#define BB 4
#define TT 32
#define NN 20000
#define NE 320000
#define DG 64
#define DW 300
#define DH 256
#define HD 128
#define H3 384
#define DESC 16
#define NC 2000

// ---------------- scratch (static device memory; no allocations) ----------------
__device__ float g_qemb[BB][DH];             // BiGRU output
__device__ float g_qg[BB][DG];               // q_emb @ W_hg + b_hg
__device__ float g_hb[NN][BB][DG];           // attn node feat projected through basis W0
__device__ float g_agg[NN][BB][DG];          // RGCN post-relu node feats
__device__ float g_s[BB][NN];                // attn2 logits
__device__ float g_stats[BB][2];             // softmax max, 1/sum
__device__ float g_nodeagg[BB][DG];
__device__ float g_hidden[BB][1024];
// CSR-by-destination
__device__ int   g_deg[NN];
__device__ int   g_off[NN + 1];
__device__ int   g_cur[NN];
__device__ int2  g_e2[NE];                   // packed {src, coef_bits}

// ---------------- kernel 0: zero + degree histogram ----------------
__global__ __launch_bounds__(256) void k0(const int* __restrict__ edst, float* __restrict__ out) {
    int i = blockIdx.x * 256 + threadIdx.x;
    if (i < NN) g_deg[i] = 0;
    // ensure zeroing of deg completes before hist within same thread index range:
    // different threads zero vs. hist different elements, so we need a grid-wide
    // ordering. Solve by having hist lag: zero is done by threads reading i<NN
    // and hist uses atomicAdd on values zeroed by OTHER blocks -> race.
    // Instead: deg zero here, hist moved to k_fill-precursor below.
    if (i < BB * NC) out[i] = 0.f;
    if (i < BB * DG) ((float*)g_nodeagg)[i] = 0.f;
}

__global__ __launch_bounds__(256) void k_hist(const int* __restrict__ edst) {
    int e = blockIdx.x * 256 + threadIdx.x;
    if (e < NE) atomicAdd(&g_deg[edst[e]], 1);
}

// ---------------- CSR scan (smem-staged, coalesced) ----------------
__global__ __launch_bounds__(1024) void k_scan() {
    __shared__ int sdeg[NN];          // 80KB
    __shared__ int part[1024];
    int t = threadIdx.x;
    for (int i = t; i < NN; i += 1024) sdeg[i] = g_deg[i];
    __syncthreads();
    const int CHK = 20;
    int base = t * CHK;
    int s = 0;
#pragma unroll
    for (int k = 0; k < CHK; k++) { int idx = base + k; if (idx < NN) s += sdeg[idx]; }
    part[t] = s;
    __syncthreads();
    for (int off = 1; off < 1024; off <<= 1) {
        int v = (t >= off) ? part[t - off] : 0;
        __syncthreads();
        part[t] += v;
        __syncthreads();
    }
    int run = part[t] - s;
    int loc[CHK];
#pragma unroll
    for (int k = 0; k < CHK; k++) {
        int idx = base + k;
        int d = (idx < NN) ? sdeg[idx] : 0;
        loc[k] = run;
        run += d;
    }
    __syncthreads();
#pragma unroll
    for (int k = 0; k < CHK; k++) { int idx = base + k; if (idx < NN) sdeg[idx] = loc[k]; }
    __syncthreads();
    for (int i = t; i < NN; i += 1024) { int v = sdeg[i]; g_off[i] = v; g_cur[i] = v; }
    if (t == 1023) g_off[NN] = part[1023];
}

__global__ __launch_bounds__(256) void k_fill(
    const int* __restrict__ esrc, const int* __restrict__ edst,
    const int* __restrict__ etype, const float* __restrict__ wcomp) {
    int e = blockIdx.x * 256 + threadIdx.x;
    if (e >= NE) return;
    int d = edst[e];
    int pos = atomicAdd(&g_cur[d], 1);
    g_e2[pos] = make_int2(esrc[e], __float_as_int(wcomp[etype[e]]));
}

// ---------------- fused gx + GRU scan: 8 blocks (dir x batch) x 768 threads ----------------
__global__ __launch_bounds__(768, 1) void k_gxgru(
    const int* __restrict__ questions, const float* __restrict__ emb_word,
    const float* __restrict__ Wxf, const float* __restrict__ bxf,
    const float* __restrict__ Wxb, const float* __restrict__ bxb,
    const float* __restrict__ Whf, const float* __restrict__ bhf,
    const float* __restrict__ Whb, const float* __restrict__ bhb)
{
    extern __shared__ float dyn[];
    float* xs = dyn;                 // [TT][DW]   9600 floats
    float* gx = dyn + TT * DW;       // [TT][H3]  12288 floats
    __shared__ float hs[HD];
    __shared__ float gsh[H3];
    __shared__ int msk[TT];
    int blk = blockIdx.x;
    int dir = blk >> 2, b = blk & 3;
    const float* Wx = dir ? Wxb : Wxf;
    const float* bx = dir ? bxb : bxf;
    const float* Wh = dir ? Whb : Whf;
    const float* bh = dir ? bhb : bhf;
    int tid = threadIdx.x;
    if (tid < TT) msk[tid] = questions[b * TT + tid];
    if (tid < HD) hs[tid] = 0.f;
    __syncthreads();
    // load word embeddings for all timesteps (coalesced)
    for (int i = tid; i < TT * DW; i += 768) {
        int t = i / DW, k = i - t * DW;
        xs[i] = emb_word[(size_t)msk[t] * DW + k];
    }
    __syncthreads();
    // gx[t][g] = bx[g] + sum_i xs[t][i]*Wx[i][g]; thread owns g, strides over t
    {
        int g = tid % H3, tp = tid / H3;  // tp in 0..1
        for (int t = tp; t < TT; t += 2) {
            int ts = dir ? (TT - 1 - t) : t;   // scan-step index
            float a0 = 0.f, a1 = 0.f, a2 = 0.f, a3 = 0.f;
            const float* x = xs + t * DW;
#pragma unroll 4
            for (int i = 0; i < DW; i += 4) {
                a0 += x[i] * Wx[i * H3 + g];
                a1 += x[i + 1] * Wx[(i + 1) * H3 + g];
                a2 += x[i + 2] * Wx[(i + 2) * H3 + g];
                a3 += x[i + 3] * Wx[(i + 3) * H3 + g];
            }
            gx[ts * H3 + g] = bx[g] + a0 + a1 + a2 + a3;
        }
    }
    // GRU scan (Wh register-resident: 2 threads per column, 64 weights each)
    int col = tid >> 1, half = tid & 1;
    float w[64];
#pragma unroll
    for (int k = 0; k < 64; k++) w[k] = Wh[(half * 64 + k) * H3 + col];
    float bias = bh[col];
    __syncthreads();
    for (int t = 0; t < TT; t++) {
        float a0 = 0.f, a1 = 0.f, a2 = 0.f, a3 = 0.f;
#pragma unroll
        for (int k = 0; k < 64; k += 4) {
            a0 += hs[half * 64 + k] * w[k];
            a1 += hs[half * 64 + k + 1] * w[k + 1];
            a2 += hs[half * 64 + k + 2] * w[k + 2];
            a3 += hs[half * 64 + k + 3] * w[k + 3];
        }
        float acc = (a0 + a1) + (a2 + a3);
        acc += __shfl_xor_sync(0xffffffffu, acc, 1);
        if (half == 0) gsh[col] = acc + bias;
        __syncthreads();
        if (tid < HD) {
            const float* gxt = gx + t * H3;
            float r = 1.f / (1.f + expf(-(gxt[tid] + gsh[tid])));
            float z = 1.f / (1.f + expf(-(gxt[HD + tid] + gsh[HD + tid])));
            float n = tanhf(gxt[2 * HD + tid] + r * gsh[2 * HD + tid]);
            float h = hs[tid];
            float hnew = (1.f - z) * n + z * h;
            int torig = dir ? (TT - 1 - t) : t;
            hs[tid] = (msk[torig] != 0) ? hnew : h;
        }
        __syncthreads();
    }
    if (tid < HD) g_qemb[b][dir * HD + tid] = hs[tid];
}

// ---------------- q_g = q_emb @ W_hg + b_hg (32 blocks) ----------------
__global__ __launch_bounds__(256) void k_qg(const float* __restrict__ Whg, const float* __restrict__ bhg) {
    int blk = blockIdx.x;
    int b = blk >> 3, og = blk & 7;
    int i = threadIdx.x;
    float x = g_qemb[b][i];
    const float4* W4 = (const float4*)Whg;
    float4 wA = W4[i * 16 + og * 2];
    float4 wB = W4[i * 16 + og * 2 + 1];
    float p[8] = { x * wA.x, x * wA.y, x * wA.z, x * wA.w,
                   x * wB.x, x * wB.y, x * wB.z, x * wB.w };
#pragma unroll
    for (int o = 0; o < 8; o++)
#pragma unroll
        for (int off = 16; off; off >>= 1)
            p[o] += __shfl_down_sync(0xffffffffu, p[o], off);
    __shared__ float red[8][8];
    int wid = i >> 5, lane = i & 31;
    if (lane == 0)
#pragma unroll
        for (int o = 0; o < 8; o++) red[o][wid] = p[o];
    __syncthreads();
    if (i < 8) {
        float s = bhg[og * 8 + i];
#pragma unroll
        for (int k = 0; k < 8; k++) s += red[i][k];
        g_qg[b][og * 8 + i] = s;
    }
}

// ---------------- node attention + basis projection: 8 nodes/block ----------------
__global__ __launch_bounds__(256) void k_nodefeat(
    const int* __restrict__ node_descs, const float* __restrict__ emb_desc,
    const float* __restrict__ bases)
{
    extern __shared__ float dyn[];
    float* sW0 = dyn;                          // [DG][DG] 4096
    float* sDesc = dyn + DG * DG;              // [8][DESC][DG+2] 8448
    float* sF = sDesc + 8 * DESC * (DG + 2);   // [8][BB][DG] 2048
    __shared__ float sQg[BB][DG];
    __shared__ float sLog[8][BB * DESC];
    __shared__ float sWt[8][BB][DESC];
    int tid = threadIdx.x;
    for (int i = tid; i < DG * DG; i += 256) sW0[i] = bases[i];
    for (int i = tid; i < BB * DG; i += 256) ((float*)sQg)[i] = ((const float*)g_qg)[i];
    __syncthreads();

    int w = tid >> 5, lane = tid & 31;
    int n = blockIdx.x * 8 + w;
    if (n >= NN) return;
    float* myDesc = sDesc + w * DESC * (DG + 2);

    int tok = 0;
    if (lane < DESC) tok = node_descs[n * DESC + lane];
    int tis[DESC];
#pragma unroll
    for (int i = 0; i < DESC; i++) tis[i] = __shfl_sync(0xffffffffu, tok, i);
#pragma unroll
    for (int i = 0; i < DESC; i++) {
        float2 v = ((const float2*)(emb_desc + (size_t)tis[i] * DG))[lane];
        *(float2*)&myDesc[i * (DG + 2) + 2 * lane] = v;
    }
    __syncwarp();

#pragma unroll
    for (int p2 = 0; p2 < 2; p2++) {
        int p = 2 * lane + p2;
        int b = p >> 4, i = p & 15;
        float acc = 0.f;
#pragma unroll
        for (int d = 0; d < DG; d++) acc += myDesc[i * (DG + 2) + d] * sQg[b][d];
        sLog[w][p] = acc;
    }
    __syncwarp();

    if (lane < BB) {
        float m = -1e30f;
#pragma unroll
        for (int i = 0; i < DESC; i++) m = fmaxf(m, sLog[w][lane * 16 + i]);
        float e[DESC];
        float s = 0.f;
#pragma unroll
        for (int i = 0; i < DESC; i++) { e[i] = expf(sLog[w][lane * 16 + i] - m); s += e[i]; }
        float inv = 1.f / s;
#pragma unroll
        for (int i = 0; i < DESC; i++) sWt[w][lane][i] = e[i] * inv;
    }
    __syncwarp();

#pragma unroll
    for (int b = 0; b < BB; b++) {
        float a0 = 0.f, a1 = 0.f;
#pragma unroll
        for (int i = 0; i < DESC; i++) {
            float wt = sWt[w][b][i];
            float2 dv = *(float2*)&myDesc[i * (DG + 2) + 2 * lane];
            a0 += wt * dv.x;
            a1 += wt * dv.y;
        }
        *(float2*)&sF[(w * BB + b) * DG + 2 * lane] = make_float2(a0, a1);
    }
    __syncwarp();

    float acc[BB][2] = {};
#pragma unroll
    for (int d = 0; d < DG; d++) {
        float2 wv = *(float2*)&sW0[d * DG + 2 * lane];
#pragma unroll
        for (int b = 0; b < BB; b++) {
            float fv = sF[(w * BB + b) * DG + d];
            acc[b][0] += fv * wv.x;
            acc[b][1] += fv * wv.y;
        }
    }
#pragma unroll
    for (int b = 0; b < BB; b++)
        *(float2*)&g_hb[n][b][2 * lane] = make_float2(acc[b][0], acc[b][1]);
}

// ---------------- CSR gather + bias/relu + attn2 logits: 2 warps per node ----------------
__global__ __launch_bounds__(256) void k_gather(const float* __restrict__ rbias) {
    int w = threadIdx.x >> 5, lane = threadIdx.x & 31;
    int n = blockIdx.x * 4 + (w >> 1);
    int half = w & 1;                 // batches 2*half .. 2*half+1
    if (n >= NN) return;
    int off = g_off[n], end = g_off[n + 1];
    float4 aA = make_float4(0.f, 0.f, 0.f, 0.f);
    float4 aB = make_float4(0.f, 0.f, 0.f, 0.f);
    const float4* hb4 = (const float4*)g_hb;
    for (int base = off; base < end; base += 32) {
        int ii = base + lane;
        int2 ed = (ii < end) ? g_e2[ii] : make_int2(0, 0);
        int m = min(32, end - base);
        int j = 0;
        for (; j + 2 <= m; j += 2) {
            int s0 = __shfl_sync(0xffffffffu, ed.x, j);
            float c0 = __int_as_float(__shfl_sync(0xffffffffu, ed.y, j));
            int s1 = __shfl_sync(0xffffffffu, ed.x, j + 1);
            float c1 = __int_as_float(__shfl_sync(0xffffffffu, ed.y, j + 1));
            float4 v0 = hb4[s0 * 64 + half * 32 + lane];
            float4 v1 = hb4[s1 * 64 + half * 32 + lane];
            aA.x += c0 * v0.x; aA.y += c0 * v0.y; aA.z += c0 * v0.z; aA.w += c0 * v0.w;
            aB.x += c1 * v1.x; aB.y += c1 * v1.y; aB.z += c1 * v1.z; aB.w += c1 * v1.w;
        }
        if (j < m) {
            int s0 = __shfl_sync(0xffffffffu, ed.x, j);
            float c0 = __int_as_float(__shfl_sync(0xffffffffu, ed.y, j));
            float4 v0 = hb4[s0 * 64 + half * 32 + lane];
            aA.x += c0 * v0.x; aA.y += c0 * v0.y; aA.z += c0 * v0.z; aA.w += c0 * v0.w;
        }
    }
    float4 a = make_float4(aA.x + aB.x, aA.y + aB.y, aA.z + aB.z, aA.w + aB.w);
    const float4* rb4 = (const float4*)rbias;
    float4 rb = rb4[lane & 15];
    a.x = fmaxf(a.x + rb.x, 0.f); a.y = fmaxf(a.y + rb.y, 0.f);
    a.z = fmaxf(a.z + rb.z, 0.f); a.w = fmaxf(a.w + rb.w, 0.f);
    ((float4*)g_agg)[n * 64 + half * 32 + lane] = a;
    // attn2 logits: this warp covers batches 2*half (lanes 0-15) and 2*half+1 (lanes 16-31)
    const float4* qg4 = (const float4*)g_qg;
    float4 q = qg4[half * 32 + lane];
    float p = a.x * q.x + a.y * q.y + a.z * q.z + a.w * q.w;
#pragma unroll
    for (int o = 8; o; o >>= 1) p += __shfl_down_sync(0xffffffffu, p, o, 16);
    if (lane == 0)  g_s[2 * half][n] = p;
    if (lane == 16) g_s[2 * half + 1][n] = p;
}

// ---------------- softmax stats over nodes (4 blocks) ----------------
__global__ __launch_bounds__(512) void k_stats() {
    int b = blockIdx.x, tid = threadIdx.x;
    __shared__ float red[512];
    float m = -1e30f;
    for (int n = tid; n < NN; n += 512) m = fmaxf(m, g_s[b][n]);
    red[tid] = m;
    __syncthreads();
    for (int s = 256; s; s >>= 1) {
        if (tid < s) red[tid] = fmaxf(red[tid], red[tid + s]);
        __syncthreads();
    }
    m = red[0];
    __syncthreads();
    float sum = 0.f;
    for (int n = tid; n < NN; n += 512) sum += expf(g_s[b][n] - m);
    red[tid] = sum;
    __syncthreads();
    for (int s = 256; s; s >>= 1) {
        if (tid < s) red[tid] += red[tid + s];
        __syncthreads();
    }
    if (tid == 0) { g_stats[b][0] = m; g_stats[b][1] = 1.f / red[0]; }
}

// ---------------- attention pooling over nodes ----------------
#define CH 256
__global__ __launch_bounds__(256) void k_pool() {
    const int nch = (NN + CH - 1) / CH;
    int b = blockIdx.x / nch, c = blockIdx.x % nch;
    int n0 = c * CH;
    __shared__ float p[CH];
    __shared__ float part[4][DG];
    int tid = threadIdx.x;
    float m = g_stats[b][0], inv = g_stats[b][1];
    int n = n0 + tid;
    p[tid] = (n < NN) ? expf(g_s[b][n] - m) * inv : 0.f;
    __syncthreads();
    int d = tid & 63, g = tid >> 6;
    float acc = 0.f;
    for (int nl = g; nl < CH; nl += 4) {
        int nn2 = n0 + nl;
        if (nn2 < NN) acc += p[nl] * g_agg[nn2][b][d];
    }
    part[g][d] = acc;
    __syncthreads();
    if (tid < DG)
        atomicAdd(&g_nodeagg[b][tid], part[0][tid] + part[1][tid] + part[2][tid] + part[3][tid]);
}

// ---------------- classifier ----------------
__global__ __launch_bounds__(256) void k_fc1(const float* __restrict__ W1, const float* __restrict__ b1) {
    __shared__ float feat[BB][DG + DH];
    int tid = threadIdx.x;
    for (int i = tid; i < BB * (DG + DH); i += 256) {
        int b = i / (DG + DH), k = i % (DG + DH);
        feat[b][k] = (k < DG) ? g_nodeagg[b][k] : g_qemb[b][k - DG];
    }
    __syncthreads();
    int j = blockIdx.x * 256 + tid;
    float acc[BB] = {};
    for (int i = 0; i < DG + DH; i++) {
        float w = W1[i * 1024 + j];
#pragma unroll
        for (int b = 0; b < BB; b++) acc[b] += feat[b][i] * w;
    }
    float bj = b1[j];
#pragma unroll
    for (int b = 0; b < BB; b++) g_hidden[b][j] = fmaxf(acc[b] + bj, 0.f);
}

__global__ __launch_bounds__(256) void k_fc2(const float* __restrict__ W2, const float* __restrict__ b2,
                                             float* __restrict__ out) {
    int jb = blockIdx.x & 7, chunk = blockIdx.x >> 3;
    __shared__ float h[BB][256];
    int tid = threadIdx.x;
    for (int idx = tid; idx < BB * 256; idx += 256) {
        int b = idx >> 8, ii = idx & 255;
        h[b][ii] = g_hidden[b][chunk * 256 + ii];
    }
    __syncthreads();
    int j = jb * 256 + tid;
    if (j >= NC) return;
    float acc[BB] = {};
    for (int i = 0; i < 256; i++) {
        float w = W2[(size_t)(chunk * 256 + i) * NC + j];
#pragma unroll
        for (int b = 0; b < BB; b++) acc[b] += h[b][i] * w;
    }
    float bj = (chunk == 0) ? b2[j] : 0.f;
#pragma unroll
    for (int b = 0; b < BB; b++) atomicAdd(&out[b * NC + j], acc[b] + bj);
}

// ---------------- launch ----------------
extern "C" void kernel_launch(void* const* d_in, const int* in_sizes, int n_in,
                              void* d_out, int out_size) {
    const int*   questions  = (const int*)d_in[0];
    const int*   node_descs = (const int*)d_in[1];
    const int*   edge_src   = (const int*)d_in[2];
    const int*   edge_dst   = (const int*)d_in[3];
    const int*   edge_type  = (const int*)d_in[4];
    const float* emb_word   = (const float*)d_in[5];
    const float* emb_desc   = (const float*)d_in[6];
    const float* Wx_f       = (const float*)d_in[7];
    const float* Wh_f       = (const float*)d_in[8];
    const float* bx_f       = (const float*)d_in[9];
    const float* bh_f       = (const float*)d_in[10];
    const float* Wx_b       = (const float*)d_in[11];
    const float* Wh_b       = (const float*)d_in[12];
    const float* bx_b       = (const float*)d_in[13];
    const float* bh_b       = (const float*)d_in[14];
    const float* W_hg       = (const float*)d_in[15];
    const float* b_hg       = (const float*)d_in[16];
    const float* bases      = (const float*)d_in[17];
    const float* w_comp     = (const float*)d_in[18];
    const float* rgcn_bias  = (const float*)d_in[19];
    const float* W1         = (const float*)d_in[20];
    const float* b1         = (const float*)d_in[21];
    const float* W2         = (const float*)d_in[22];
    const float* b2         = (const float*)d_in[23];
    float* out = (float*)d_out;

    static int inited = 0;
    if (!inited) {
        cudaFuncSetAttribute(k_gxgru, cudaFuncAttributeMaxDynamicSharedMemorySize,
                             (TT * DW + TT * H3) * 4);
        cudaFuncSetAttribute(k_nodefeat, cudaFuncAttributeMaxDynamicSharedMemorySize,
                             (DG * DG + 8 * DESC * (DG + 2) + 8 * BB * DG) * 4);
        inited = 1;
    }

    k0<<<(NN + 255) / 256, 256>>>(edge_dst, out);
    k_gxgru<<<8, 768, (TT * DW + TT * H3) * 4>>>(questions, emb_word,
        Wx_f, bx_f, Wx_b, bx_b, Wh_f, bh_f, Wh_b, bh_b);
    k_qg<<<32, 256>>>(W_hg, b_hg);
    k_nodefeat<<<(NN + 7) / 8, 256, (DG * DG + 8 * DESC * (DG + 2) + 8 * BB * DG) * 4>>>(
        node_descs, emb_desc, bases);                       // <- 4th launch (profiled)
    k_hist<<<(NE + 255) / 256, 256>>>(edge_dst);
    k_scan<<<1, 1024>>>();
    k_fill<<<(NE + 255) / 256, 256>>>(edge_src, edge_dst, edge_type, w_comp);
    k_gather<<<(NN + 3) / 4, 256>>>(rgcn_bias);
    k_stats<<<4, 512>>>();
    k_pool<<<4 * ((NN + CH - 1) / CH), 256>>>();
    k_fc1<<<4, 256>>>(W1, b1);
    k_fc2<<<32, 256>>>(W2, b2, out);
}

// round 5
// speedup vs baseline: 2.3130x; 1.1107x over previous
#include <cuda_runtime.h>
#include <math.h>

#define BB 4
#define TT 32
#define NN 20000
#define NE 320000
#define DG 64
#define DW 300
#define DH 256
#define HD 128
#define H3 384
#define DESC 16
#define NC 2000
#define VD 30000

// ---------------- scratch (static device memory; no allocations) ----------------
__device__ float g_qemb[BB][DH];
__device__ float g_qg[BB][DG];
__device__ float4 g_tokdot[VD];              // per-token dot with q_g (4 batches)
__device__ float g_P[(size_t)VD * DG];       // emb_desc @ W0
__device__ float g_hb[NN][BB][DG];
__device__ float g_agg[NN][BB][DG];
__device__ float g_s[BB][NN];
__device__ float g_stats[BB][2];
__device__ float g_nodeagg[BB][DG];
__device__ float g_hidden[BB][1024];
// CSR-by-destination
__device__ int   g_deg[NN];
__device__ int   g_off[NN + 1];
__device__ int   g_cur[NN];
__device__ int2  g_e2[NE];

// ---------------- zero out/nodeagg (main stream) ----------------
__global__ __launch_bounds__(256) void k0(float* __restrict__ out) {
    int i = blockIdx.x * 256 + threadIdx.x;
    if (i < BB * NC) out[i] = 0.f;
    if (i < BB * DG) ((float*)g_nodeagg)[i] = 0.f;
}

// ---------------- CSR build (side stream) ----------------
__global__ __launch_bounds__(256) void k_zdeg() {
    int i = blockIdx.x * 256 + threadIdx.x;
    if (i < NN) g_deg[i] = 0;
}

__global__ __launch_bounds__(256) void k_hist(const int* __restrict__ edst) {
    int e = blockIdx.x * 256 + threadIdx.x;
    if (e < NE) atomicAdd(&g_deg[edst[e]], 1);
}

__global__ __launch_bounds__(1024) void k_scan() {
    __shared__ int sdeg[NN];
    __shared__ int part[1024];
    int t = threadIdx.x;
    for (int i = t; i < NN; i += 1024) sdeg[i] = g_deg[i];
    __syncthreads();
    const int CHK = 20;
    int base = t * CHK;
    int s = 0;
#pragma unroll
    for (int k = 0; k < CHK; k++) { int idx = base + k; if (idx < NN) s += sdeg[idx]; }
    part[t] = s;
    __syncthreads();
    for (int off = 1; off < 1024; off <<= 1) {
        int v = (t >= off) ? part[t - off] : 0;
        __syncthreads();
        part[t] += v;
        __syncthreads();
    }
    int run = part[t] - s;
    int loc[CHK];
#pragma unroll
    for (int k = 0; k < CHK; k++) {
        int idx = base + k;
        int d = (idx < NN) ? sdeg[idx] : 0;
        loc[k] = run;
        run += d;
    }
    __syncthreads();
#pragma unroll
    for (int k = 0; k < CHK; k++) { int idx = base + k; if (idx < NN) sdeg[idx] = loc[k]; }
    __syncthreads();
    for (int i = t; i < NN; i += 1024) { int v = sdeg[i]; g_off[i] = v; g_cur[i] = v; }
    if (t == 1023) g_off[NN] = part[1023];
}

__global__ __launch_bounds__(256) void k_fill(
    const int* __restrict__ esrc, const int* __restrict__ edst,
    const int* __restrict__ etype, const float* __restrict__ wcomp) {
    int e = blockIdx.x * 256 + threadIdx.x;
    if (e >= NE) return;
    int d = edst[e];
    int pos = atomicAdd(&g_cur[d], 1);
    g_e2[pos] = make_int2(esrc[e], __float_as_int(wcomp[etype[e]]));
}

// ---------------- fused gx + GRU scan: 8 blocks (dir x batch) x 768 threads ----------------
__global__ __launch_bounds__(768, 1) void k_gxgru(
    const int* __restrict__ questions, const float* __restrict__ emb_word,
    const float* __restrict__ Wxf, const float* __restrict__ bxf,
    const float* __restrict__ Wxb, const float* __restrict__ bxb,
    const float* __restrict__ Whf, const float* __restrict__ bhf,
    const float* __restrict__ Whb, const float* __restrict__ bhb)
{
    extern __shared__ float dyn[];
    float* xs = dyn;                 // [TT][DW]
    float* gx = dyn + TT * DW;       // [TT][H3]
    __shared__ float hs[HD];
    __shared__ float gsh[H3];
    __shared__ int msk[TT];
    int blk = blockIdx.x;
    int dir = blk >> 2, b = blk & 3;
    const float* Wx = dir ? Wxb : Wxf;
    const float* bx = dir ? bxb : bxf;
    const float* Wh = dir ? Whb : Whf;
    const float* bh = dir ? bhb : bhf;
    int tid = threadIdx.x;
    if (tid < TT) msk[tid] = questions[b * TT + tid];
    if (tid < HD) hs[tid] = 0.f;
    __syncthreads();
    for (int i = tid; i < TT * DW; i += 768) {
        int t = i / DW, k = i - t * DW;
        xs[i] = emb_word[(size_t)msk[t] * DW + k];
    }
    __syncthreads();
    {
        int g = tid % H3, tp = tid / H3;
        for (int t = tp; t < TT; t += 2) {
            int ts = dir ? (TT - 1 - t) : t;
            float a0 = 0.f, a1 = 0.f, a2 = 0.f, a3 = 0.f;
            const float* x = xs + t * DW;
#pragma unroll 4
            for (int i = 0; i < DW; i += 4) {
                a0 += x[i] * Wx[i * H3 + g];
                a1 += x[i + 1] * Wx[(i + 1) * H3 + g];
                a2 += x[i + 2] * Wx[(i + 2) * H3 + g];
                a3 += x[i + 3] * Wx[(i + 3) * H3 + g];
            }
            gx[ts * H3 + g] = bx[g] + a0 + a1 + a2 + a3;
        }
    }
    int col = tid >> 1, half = tid & 1;
    float w[64];
#pragma unroll
    for (int k = 0; k < 64; k++) w[k] = Wh[(half * 64 + k) * H3 + col];
    float bias = bh[col];
    __syncthreads();
    for (int t = 0; t < TT; t++) {
        float a0 = 0.f, a1 = 0.f, a2 = 0.f, a3 = 0.f;
#pragma unroll
        for (int k = 0; k < 64; k += 4) {
            a0 += hs[half * 64 + k] * w[k];
            a1 += hs[half * 64 + k + 1] * w[k + 1];
            a2 += hs[half * 64 + k + 2] * w[k + 2];
            a3 += hs[half * 64 + k + 3] * w[k + 3];
        }
        float acc = (a0 + a1) + (a2 + a3);
        acc += __shfl_xor_sync(0xffffffffu, acc, 1);
        if (half == 0) gsh[col] = acc + bias;
        __syncthreads();
        if (tid < HD) {
            const float* gxt = gx + t * H3;
            float r = 1.f / (1.f + expf(-(gxt[tid] + gsh[tid])));
            float z = 1.f / (1.f + expf(-(gxt[HD + tid] + gsh[HD + tid])));
            float n = tanhf(gxt[2 * HD + tid] + r * gsh[2 * HD + tid]);
            float h = hs[tid];
            float hnew = (1.f - z) * n + z * h;
            int torig = dir ? (TT - 1 - t) : t;
            hs[tid] = (msk[torig] != 0) ? hnew : h;
        }
        __syncthreads();
    }
    if (tid < HD) g_qemb[b][dir * HD + tid] = hs[tid];
}

// ---------------- q_g = q_emb @ W_hg + b_hg (32 blocks) ----------------
__global__ __launch_bounds__(256) void k_qg(const float* __restrict__ Whg, const float* __restrict__ bhg) {
    int blk = blockIdx.x;
    int b = blk >> 3, og = blk & 7;
    int i = threadIdx.x;
    float x = g_qemb[b][i];
    const float4* W4 = (const float4*)Whg;
    float4 wA = W4[i * 16 + og * 2];
    float4 wB = W4[i * 16 + og * 2 + 1];
    float p[8] = { x * wA.x, x * wA.y, x * wA.z, x * wA.w,
                   x * wB.x, x * wB.y, x * wB.z, x * wB.w };
#pragma unroll
    for (int o = 0; o < 8; o++)
#pragma unroll
        for (int off = 16; off; off >>= 1)
            p[o] += __shfl_down_sync(0xffffffffu, p[o], off);
    __shared__ float red[8][8];
    int wid = i >> 5, lane = i & 31;
    if (lane == 0)
#pragma unroll
        for (int o = 0; o < 8; o++) red[o][wid] = p[o];
    __syncthreads();
    if (i < 8) {
        float s = bhg[og * 8 + i];
#pragma unroll
        for (int k = 0; k < 8; k++) s += red[i][k];
        g_qg[b][og * 8 + i] = s;
    }
}

// ---------------- per-token precompute: tokdot[v][b] and P = emb_desc @ W0 ----------------
// one warp per token, 8 warps/block, 3750 blocks
__global__ __launch_bounds__(256) void k_tok(
    const float* __restrict__ emb_desc, const float* __restrict__ bases)
{
    __shared__ float sW0[DG * DG];
    __shared__ float sQg[BB][DG];
    __shared__ float sE[8][DG];
    int tid = threadIdx.x;
    for (int i = tid; i < DG * DG; i += 256) sW0[i] = bases[i];
    for (int i = tid; i < BB * DG; i += 256) ((float*)sQg)[i] = ((const float*)g_qg)[i];
    __syncthreads();
    int w = tid >> 5, lane = tid & 31;
    int v = blockIdx.x * 8 + w;
    if (v >= VD) return;
    float2 e = ((const float2*)(emb_desc + (size_t)v * DG))[lane];
    sE[w][2 * lane] = e.x;
    sE[w][2 * lane + 1] = e.y;
    __syncwarp();
    // token dot with q_g (4 batches)
    float p0 = e.x * sQg[0][2 * lane] + e.y * sQg[0][2 * lane + 1];
    float p1 = e.x * sQg[1][2 * lane] + e.y * sQg[1][2 * lane + 1];
    float p2 = e.x * sQg[2][2 * lane] + e.y * sQg[2][2 * lane + 1];
    float p3 = e.x * sQg[3][2 * lane] + e.y * sQg[3][2 * lane + 1];
#pragma unroll
    for (int off = 16; off; off >>= 1) {
        p0 += __shfl_xor_sync(0xffffffffu, p0, off);
        p1 += __shfl_xor_sync(0xffffffffu, p1, off);
        p2 += __shfl_xor_sync(0xffffffffu, p2, off);
        p3 += __shfl_xor_sync(0xffffffffu, p3, off);
    }
    if (lane == 0) g_tokdot[v] = make_float4(p0, p1, p2, p3);
    // P row: emb_row @ W0 (lane owns dims 2l, 2l+1)
    float ax = 0.f, ay = 0.f;
#pragma unroll
    for (int d = 0; d < DG; d++) {
        float fv = sE[w][d];
        float2 wv = *(float2*)&sW0[d * DG + 2 * lane];
        ax += fv * wv.x;
        ay += fv * wv.y;
    }
    ((float2*)(g_P + (size_t)v * DG))[lane] = make_float2(ax, ay);
}

// ---------------- per-node: softmax over gathered tokdots + weighted sum of P rows ----------------
// one warp per node, 8 warps/block, 2500 blocks
__global__ __launch_bounds__(256) void k_node(const int* __restrict__ node_descs) {
    int tid = threadIdx.x;
    int w = tid >> 5, lane = tid & 31;
    int n = blockIdx.x * 8 + w;
    if (n >= NN) return;
    int tok = 0;
    float4 dv = make_float4(-1e30f, -1e30f, -1e30f, -1e30f);
    if (lane < DESC) {
        tok = node_descs[n * DESC + lane];
        dv = g_tokdot[tok];
    }
    // softmax over 16 lanes (width-16 butterflies), per batch component
    float4 m = dv;
#pragma unroll
    for (int off = 8; off; off >>= 1) {
        m.x = fmaxf(m.x, __shfl_xor_sync(0xffffffffu, m.x, off, 16));
        m.y = fmaxf(m.y, __shfl_xor_sync(0xffffffffu, m.y, off, 16));
        m.z = fmaxf(m.z, __shfl_xor_sync(0xffffffffu, m.z, off, 16));
        m.w = fmaxf(m.w, __shfl_xor_sync(0xffffffffu, m.w, off, 16));
    }
    float4 ev;
    ev.x = expf(dv.x - m.x); ev.y = expf(dv.y - m.y);
    ev.z = expf(dv.z - m.z); ev.w = expf(dv.w - m.w);
    float4 s = ev;
#pragma unroll
    for (int off = 8; off; off >>= 1) {
        s.x += __shfl_xor_sync(0xffffffffu, s.x, off, 16);
        s.y += __shfl_xor_sync(0xffffffffu, s.y, off, 16);
        s.z += __shfl_xor_sync(0xffffffffu, s.z, off, 16);
        s.w += __shfl_xor_sync(0xffffffffu, s.w, off, 16);
    }
    float4 wt;
    wt.x = ev.x / s.x; wt.y = ev.y / s.y; wt.z = ev.z / s.z; wt.w = ev.w / s.w;
    // weighted sum of P rows; lane owns dims 2l, 2l+1
    float2 acc0 = make_float2(0.f, 0.f), acc1 = acc0, acc2 = acc0, acc3 = acc0;
#pragma unroll
    for (int i = 0; i < DESC; i++) {
        int ti = __shfl_sync(0xffffffffu, tok, i);
        float w0 = __shfl_sync(0xffffffffu, wt.x, i);
        float w1 = __shfl_sync(0xffffffffu, wt.y, i);
        float w2 = __shfl_sync(0xffffffffu, wt.z, i);
        float w3 = __shfl_sync(0xffffffffu, wt.w, i);
        float2 pv = ((const float2*)(g_P + (size_t)ti * DG))[lane];
        acc0.x += w0 * pv.x; acc0.y += w0 * pv.y;
        acc1.x += w1 * pv.x; acc1.y += w1 * pv.y;
        acc2.x += w2 * pv.x; acc2.y += w2 * pv.y;
        acc3.x += w3 * pv.x; acc3.y += w3 * pv.y;
    }
    ((float2*)&g_hb[n][0][0])[lane] = acc0;
    ((float2*)&g_hb[n][1][0])[lane] = acc1;
    ((float2*)&g_hb[n][2][0])[lane] = acc2;
    ((float2*)&g_hb[n][3][0])[lane] = acc3;
}

// ---------------- CSR gather + bias/relu + attn2 logits: 2 warps per node ----------------
__global__ __launch_bounds__(256) void k_gather(const float* __restrict__ rbias) {
    int w = threadIdx.x >> 5, lane = threadIdx.x & 31;
    int n = blockIdx.x * 4 + (w >> 1);
    int half = w & 1;
    if (n >= NN) return;
    int off = g_off[n], end = g_off[n + 1];
    float4 aA = make_float4(0.f, 0.f, 0.f, 0.f);
    float4 aB = make_float4(0.f, 0.f, 0.f, 0.f);
    const float4* hb4 = (const float4*)g_hb;
    for (int base = off; base < end; base += 32) {
        int ii = base + lane;
        int2 ed = (ii < end) ? g_e2[ii] : make_int2(0, 0);
        int m = min(32, end - base);
        int j = 0;
        for (; j + 2 <= m; j += 2) {
            int s0 = __shfl_sync(0xffffffffu, ed.x, j);
            float c0 = __int_as_float(__shfl_sync(0xffffffffu, ed.y, j));
            int s1 = __shfl_sync(0xffffffffu, ed.x, j + 1);
            float c1 = __int_as_float(__shfl_sync(0xffffffffu, ed.y, j + 1));
            float4 v0 = hb4[s0 * 64 + half * 32 + lane];
            float4 v1 = hb4[s1 * 64 + half * 32 + lane];
            aA.x += c0 * v0.x; aA.y += c0 * v0.y; aA.z += c0 * v0.z; aA.w += c0 * v0.w;
            aB.x += c1 * v1.x; aB.y += c1 * v1.y; aB.z += c1 * v1.z; aB.w += c1 * v1.w;
        }
        if (j < m) {
            int s0 = __shfl_sync(0xffffffffu, ed.x, j);
            float c0 = __int_as_float(__shfl_sync(0xffffffffu, ed.y, j));
            float4 v0 = hb4[s0 * 64 + half * 32 + lane];
            aA.x += c0 * v0.x; aA.y += c0 * v0.y; aA.z += c0 * v0.z; aA.w += c0 * v0.w;
        }
    }
    float4 a = make_float4(aA.x + aB.x, aA.y + aB.y, aA.z + aB.z, aA.w + aB.w);
    const float4* rb4 = (const float4*)rbias;
    float4 rb = rb4[lane & 15];
    a.x = fmaxf(a.x + rb.x, 0.f); a.y = fmaxf(a.y + rb.y, 0.f);
    a.z = fmaxf(a.z + rb.z, 0.f); a.w = fmaxf(a.w + rb.w, 0.f);
    ((float4*)g_agg)[n * 64 + half * 32 + lane] = a;
    const float4* qg4 = (const float4*)g_qg;
    float4 q = qg4[half * 32 + lane];
    float p = a.x * q.x + a.y * q.y + a.z * q.z + a.w * q.w;
#pragma unroll
    for (int o = 8; o; o >>= 1) p += __shfl_down_sync(0xffffffffu, p, o, 16);
    if (lane == 0)  g_s[2 * half][n] = p;
    if (lane == 16) g_s[2 * half + 1][n] = p;
}

// ---------------- softmax stats over nodes (4 blocks) ----------------
__global__ __launch_bounds__(512) void k_stats() {
    int b = blockIdx.x, tid = threadIdx.x;
    __shared__ float red[512];
    float m = -1e30f;
    for (int n = tid; n < NN; n += 512) m = fmaxf(m, g_s[b][n]);
    red[tid] = m;
    __syncthreads();
    for (int s = 256; s; s >>= 1) {
        if (tid < s) red[tid] = fmaxf(red[tid], red[tid + s]);
        __syncthreads();
    }
    m = red[0];
    __syncthreads();
    float sum = 0.f;
    for (int n = tid; n < NN; n += 512) sum += expf(g_s[b][n] - m);
    red[tid] = sum;
    __syncthreads();
    for (int s = 256; s; s >>= 1) {
        if (tid < s) red[tid] += red[tid + s];
        __syncthreads();
    }
    if (tid == 0) { g_stats[b][0] = m; g_stats[b][1] = 1.f / red[0]; }
}

// ---------------- attention pooling over nodes ----------------
#define CH 256
__global__ __launch_bounds__(256) void k_pool() {
    const int nch = (NN + CH - 1) / CH;
    int b = blockIdx.x / nch, c = blockIdx.x % nch;
    int n0 = c * CH;
    __shared__ float p[CH];
    __shared__ float part[4][DG];
    int tid = threadIdx.x;
    float m = g_stats[b][0], inv = g_stats[b][1];
    int n = n0 + tid;
    p[tid] = (n < NN) ? expf(g_s[b][n] - m) * inv : 0.f;
    __syncthreads();
    int d = tid & 63, g = tid >> 6;
    float acc = 0.f;
    for (int nl = g; nl < CH; nl += 4) {
        int nn2 = n0 + nl;
        if (nn2 < NN) acc += p[nl] * g_agg[nn2][b][d];
    }
    part[g][d] = acc;
    __syncthreads();
    if (tid < DG)
        atomicAdd(&g_nodeagg[b][tid], part[0][tid] + part[1][tid] + part[2][tid] + part[3][tid]);
}

// ---------------- classifier ----------------
__global__ __launch_bounds__(256) void k_fc1(const float* __restrict__ W1, const float* __restrict__ b1) {
    __shared__ float feat[BB][DG + DH];
    int tid = threadIdx.x;
    for (int i = tid; i < BB * (DG + DH); i += 256) {
        int b = i / (DG + DH), k = i % (DG + DH);
        feat[b][k] = (k < DG) ? g_nodeagg[b][k] : g_qemb[b][k - DG];
    }
    __syncthreads();
    int j = blockIdx.x * 256 + tid;
    float acc[BB] = {};
    for (int i = 0; i < DG + DH; i++) {
        float w = W1[i * 1024 + j];
#pragma unroll
        for (int b = 0; b < BB; b++) acc[b] += feat[b][i] * w;
    }
    float bj = b1[j];
#pragma unroll
    for (int b = 0; b < BB; b++) g_hidden[b][j] = fmaxf(acc[b] + bj, 0.f);
}

__global__ __launch_bounds__(256) void k_fc2(const float* __restrict__ W2, const float* __restrict__ b2,
                                             float* __restrict__ out) {
    int jb = blockIdx.x & 7, chunk = blockIdx.x >> 3;
    __shared__ float h[BB][256];
    int tid = threadIdx.x;
    for (int idx = tid; idx < BB * 256; idx += 256) {
        int b = idx >> 8, ii = idx & 255;
        h[b][ii] = g_hidden[b][chunk * 256 + ii];
    }
    __syncthreads();
    int j = jb * 256 + tid;
    if (j >= NC) return;
    float acc[BB] = {};
    for (int i = 0; i < 256; i++) {
        float w = W2[(size_t)(chunk * 256 + i) * NC + j];
#pragma unroll
        for (int b = 0; b < BB; b++) acc[b] += h[b][i] * w;
    }
    float bj = (chunk == 0) ? b2[j] : 0.f;
#pragma unroll
    for (int b = 0; b < BB; b++) atomicAdd(&out[b * NC + j], acc[b] + bj);
}

// ---------------- launch ----------------
extern "C" void kernel_launch(void* const* d_in, const int* in_sizes, int n_in,
                              void* d_out, int out_size) {
    const int*   questions  = (const int*)d_in[0];
    const int*   node_descs = (const int*)d_in[1];
    const int*   edge_src   = (const int*)d_in[2];
    const int*   edge_dst   = (const int*)d_in[3];
    const int*   edge_type  = (const int*)d_in[4];
    const float* emb_word   = (const float*)d_in[5];
    const float* emb_desc   = (const float*)d_in[6];
    const float* Wx_f       = (const float*)d_in[7];
    const float* Wh_f       = (const float*)d_in[8];
    const float* bx_f       = (const float*)d_in[9];
    const float* bh_f       = (const float*)d_in[10];
    const float* Wx_b       = (const float*)d_in[11];
    const float* Wh_b       = (const float*)d_in[12];
    const float* bx_b       = (const float*)d_in[13];
    const float* bh_b       = (const float*)d_in[14];
    const float* W_hg       = (const float*)d_in[15];
    const float* b_hg       = (const float*)d_in[16];
    const float* bases      = (const float*)d_in[17];
    const float* w_comp     = (const float*)d_in[18];
    const float* rgcn_bias  = (const float*)d_in[19];
    const float* W1         = (const float*)d_in[20];
    const float* b1         = (const float*)d_in[21];
    const float* W2         = (const float*)d_in[22];
    const float* b2         = (const float*)d_in[23];
    float* out = (float*)d_out;

    static cudaStream_t s2 = 0;
    static cudaEvent_t evFork = 0, evCSR = 0;
    static int inited = 0;
    if (!inited) {
        cudaFuncSetAttribute(k_gxgru, cudaFuncAttributeMaxDynamicSharedMemorySize,
                             (TT * DW + TT * H3) * 4);
        cudaStreamCreateWithFlags(&s2, cudaStreamNonBlocking);
        cudaEventCreateWithFlags(&evFork, cudaEventDisableTiming);
        cudaEventCreateWithFlags(&evCSR, cudaEventDisableTiming);
        inited = 1;
    }

    // main stream start + fork side stream for CSR build
    k0<<<(BB * NC + 255) / 256, 256>>>(out);
    cudaEventRecord(evFork, 0);
    cudaStreamWaitEvent(s2, evFork, 0);
    k_zdeg<<<(NN + 255) / 256, 256, 0, s2>>>();
    k_hist<<<(NE + 255) / 256, 256, 0, s2>>>(edge_dst);
    k_scan<<<1, 1024, 0, s2>>>();
    k_fill<<<(NE + 255) / 256, 256, 0, s2>>>(edge_src, edge_dst, edge_type, w_comp);
    cudaEventRecord(evCSR, s2);

    // main stream: question encoding + node features
    k_gxgru<<<8, 768, (TT * DW + TT * H3) * 4>>>(questions, emb_word,
        Wx_f, bx_f, Wx_b, bx_b, Wh_f, bh_f, Wh_b, bh_b);
    k_qg<<<32, 256>>>(W_hg, b_hg);
    k_tok<<<(VD + 7) / 8, 256>>>(emb_desc, bases);
    k_node<<<(NN + 7) / 8, 256>>>(node_descs);

    // join CSR, then gather + rest
    cudaStreamWaitEvent(0, evCSR, 0);
    k_gather<<<(NN + 3) / 4, 256>>>(rgcn_bias);
    k_stats<<<4, 512>>>();
    k_pool<<<4 * ((NN + CH - 1) / CH), 256>>>();
    k_fc1<<<4, 256>>>(W1, b1);
    k_fc2<<<32, 256>>>(W2, b2, out);
}